// round 1
// baseline (speedup 1.0000x reference)
#include <cuda_runtime.h>

#define BS   4
#define SEQ  128
#define DIM  768
#define HID  768
#define NOUT 2
#define MROWS (BS * SEQ)          // 512
#define PAIR_TOT (BS * SEQ * SEQ * NOUT)   // 131072

// Scratch (device globals: no allocation allowed)
__device__ float g_ha[MROWS * HID];        // a @ W1[:D]
__device__ float g_hb[MROWS * HID];        // b @ W1[D:] + b1
__device__ float g_part[2 * PAIR_TOT];     // per-h-half partial scores

// ---------------------------------------------------------------------------
// Kernel 1: projection GEMM.  z=0: ha = a @ W1[0:768]; z=1: hb = b @ W1[768:1536] + b1
// M=512, N=768, K=768.  BM=32, BN=64, BK=16, 256 threads, 2x4 microtile.
// ---------------------------------------------------------------------------
__global__ __launch_bounds__(256) void proj_kernel(
    const float* __restrict__ a, const float* __restrict__ b,
    const float* __restrict__ W1, const float* __restrict__ b1)
{
    const int z = blockIdx.z;
    const float* __restrict__ X = z ? b : a;
    const float* __restrict__ W = W1 + (size_t)z * DIM * HID;
    float* __restrict__ outp = z ? g_hb : g_ha;

    __shared__ float As[16][34];   // [k][m], padded (34 keeps 8B align + no store conflicts)
    __shared__ float Bs[16][64];   // [k][n]

    const int tid = threadIdx.x;
    const int m0 = blockIdx.y * 32;
    const int n0 = blockIdx.x * 64;
    const int tx = tid & 15;       // n group (4 cols)
    const int ty = tid >> 4;       // m group (2 rows)

    // load assignments
    const int ar = tid >> 3;            // 0..31  (m row)
    const int ak = (tid & 7) * 2;       // 0..14  (k, float2)
    const int br = tid >> 4;            // 0..15  (k row)
    const int bc = (tid & 15) * 4;      // 0..60  (n, float4)

    float acc[2][4] = {};

    for (int k0 = 0; k0 < DIM; k0 += 16) {
        float2 av = *(const float2*)&X[(size_t)(m0 + ar) * DIM + k0 + ak];
        As[ak][ar]     = av.x;
        As[ak + 1][ar] = av.y;
        *(float4*)&Bs[br][bc] = *(const float4*)&W[(size_t)(k0 + br) * HID + n0 + bc];
        __syncthreads();

        #pragma unroll
        for (int k = 0; k < 16; k++) {
            float2 a2 = *(const float2*)&As[k][ty * 2];
            float4 b4 = *(const float4*)&Bs[k][tx * 4];
            acc[0][0] += a2.x * b4.x;  acc[0][1] += a2.x * b4.y;
            acc[0][2] += a2.x * b4.z;  acc[0][3] += a2.x * b4.w;
            acc[1][0] += a2.y * b4.x;  acc[1][1] += a2.y * b4.y;
            acc[1][2] += a2.y * b4.z;  acc[1][3] += a2.y * b4.w;
        }
        __syncthreads();
    }

    float4 bias = make_float4(0.f, 0.f, 0.f, 0.f);
    if (z) bias = *(const float4*)&b1[n0 + tx * 4];

    #pragma unroll
    for (int i = 0; i < 2; i++) {
        float4 v = make_float4(acc[i][0] + bias.x, acc[i][1] + bias.y,
                               acc[i][2] + bias.z, acc[i][3] + bias.w);
        *(float4*)&outp[(size_t)(m0 + ty * 2 + i) * HID + n0 + tx * 4] = v;
    }
}

// ---------------------------------------------------------------------------
// Kernel 2: pairwise relu + reduce to O=2.
// Grid: (t_tile=4, s_tile=4, batch*2 + h_half = 8) -> 128 CTAs (one full wave).
// 256 threads, 32x32 pair tile, 2x2 pairs per thread, H chunked by 64 in smem.
// Writes fp32 partials per h-half (deterministic; combined in kernel 3).
// ---------------------------------------------------------------------------
#define HC 64
__global__ __launch_bounds__(256) void pair_kernel(const float* __restrict__ W2)
{
    const int tt = blockIdx.x;            // t tile
    const int st = blockIdx.y;            // s tile
    const int zb = blockIdx.z;
    const int batch = zb >> 1;
    const int hh = zb & 1;
    const int h0base = hh * (HID / 2);    // 0 or 384

    __shared__ float sha[32][HC];         // [s_local][h]  (reads broadcast)
    __shared__ float shT[HC][32];         // [h][t_local]  (reads LDS.64, conflict-free)
    __shared__ float sw[HC * 2];          // W2 chunk

    const int tid = threadIdx.x;
    const int tq = tid & 15;              // t quad (2 cols)
    const int sq = tid >> 4;              // s quad (2 rows)

    const float* __restrict__ hap = g_ha + (size_t)(batch * SEQ + st * 32) * HID;
    const float* __restrict__ hbp = g_hb + (size_t)(batch * SEQ + tt * 32) * HID;

    // load assignments
    const int lr = tid >> 3;              // 0..31  s row
    const int lc = (tid & 7) * 8;         // h group of 8
    const int tr = tid & 31;              // 0..31  t row
    const int th = (tid >> 5) * 8;        // h group of 8

    float acc[2][2][2] = {};

    for (int hc = 0; hc < HID / 2; hc += HC) {
        const int h0 = h0base + hc;

        *(float4*)&sha[lr][lc]     = *(const float4*)&hap[(size_t)lr * HID + h0 + lc];
        *(float4*)&sha[lr][lc + 4] = *(const float4*)&hap[(size_t)lr * HID + h0 + lc + 4];

        float4 v0 = *(const float4*)&hbp[(size_t)tr * HID + h0 + th];
        float4 v1 = *(const float4*)&hbp[(size_t)tr * HID + h0 + th + 4];
        shT[th + 0][tr] = v0.x;  shT[th + 1][tr] = v0.y;
        shT[th + 2][tr] = v0.z;  shT[th + 3][tr] = v0.w;
        shT[th + 4][tr] = v1.x;  shT[th + 5][tr] = v1.y;
        shT[th + 6][tr] = v1.z;  shT[th + 7][tr] = v1.w;

        if (tid < 32)
            *(float4*)&sw[tid * 4] = *(const float4*)&W2[h0 * 2 + tid * 4];
        __syncthreads();

        #pragma unroll 16
        for (int h = 0; h < HC; h++) {
            float a0 = sha[sq * 2][h];
            float a1 = sha[sq * 2 + 1][h];
            float2 bb = *(const float2*)&shT[h][tq * 2];
            float2 wv = *(const float2*)&sw[h * 2];
            float r;
            r = fmaxf(a0 + bb.x, 0.f); acc[0][0][0] += r * wv.x; acc[0][0][1] += r * wv.y;
            r = fmaxf(a0 + bb.y, 0.f); acc[0][1][0] += r * wv.x; acc[0][1][1] += r * wv.y;
            r = fmaxf(a1 + bb.x, 0.f); acc[1][0][0] += r * wv.x; acc[1][0][1] += r * wv.y;
            r = fmaxf(a1 + bb.y, 0.f); acc[1][1][0] += r * wv.x; acc[1][1][1] += r * wv.y;
        }
        __syncthreads();
    }

    float* __restrict__ pp = g_part + (size_t)hh * PAIR_TOT;
    #pragma unroll
    for (int i = 0; i < 2; i++) {
        #pragma unroll
        for (int j = 0; j < 2; j++) {
            int s = st * 32 + sq * 2 + i;
            int t = tt * 32 + tq * 2 + j;
            size_t idx = (((size_t)batch * SEQ + s) * SEQ + t) * NOUT;
            *(float2*)&pp[idx] = make_float2(acc[i][j][0], acc[i][j][1]);
        }
    }
}

// ---------------------------------------------------------------------------
// Kernel 3: deterministic combine of the two h-halves + b2.
// ---------------------------------------------------------------------------
__global__ __launch_bounds__(256) void combine_kernel(
    float* __restrict__ out, const float* __restrict__ b2)
{
    int i = blockIdx.x * 256 + threadIdx.x;    // float4 index; PAIR_TOT/4 = 32768
    float4 p0 = *(const float4*)&g_part[(size_t)i * 4];
    float4 p1 = *(const float4*)&g_part[(size_t)PAIR_TOT + (size_t)i * 4];
    float c0 = b2[0], c1 = b2[1];
    float4 v = make_float4(p0.x + p1.x + c0, p0.y + p1.y + c1,
                           p0.z + p1.z + c0, p0.w + p1.w + c1);
    *(float4*)&out[(size_t)i * 4] = v;
}

// ---------------------------------------------------------------------------
extern "C" void kernel_launch(void* const* d_in, const int* in_sizes, int n_in,
                              void* d_out, int out_size)
{
    const float* a  = (const float*)d_in[0];
    const float* b  = (const float*)d_in[1];
    const float* W1 = (const float*)d_in[2];
    const float* b1 = (const float*)d_in[3];
    const float* W2 = (const float*)d_in[4];
    const float* b2 = (const float*)d_in[5];
    float* out = (float*)d_out;

    proj_kernel<<<dim3(HID / 64, MROWS / 32, 2), 256>>>(a, b, W1, b1);
    pair_kernel<<<dim3(SEQ / 32, SEQ / 32, BS * 2), 256>>>(W2);
    combine_kernel<<<PAIR_TOT / 4 / 256, 256>>>(out, b2);
}

// round 3
// speedup vs baseline: 1.8525x; 1.8525x over previous
#include <cuda_runtime.h>
#include <cstdint>

#define BS   4
#define SEQ  128
#define DIM  768
#define HID  768
#define NOUT 2
#define MROWS (BS * SEQ)                    // 512
#define PAIR_TOT (BS * SEQ * SEQ * NOUT)    // 131072

// ---------------- device scratch (no allocation allowed) -------------------
__device__ float g_ha[MROWS * HID];         // a @ W1[:D]
__device__ float g_hb[MROWS * HID];         // b @ W1[D:] + b1
__device__ float g_part[2 * PAIR_TOT];      // per-h-half partial scores

// ---------------------------------------------------------------------------
__device__ __forceinline__ uint32_t smem_u32(const void* p) {
    uint32_t a;
    asm("{ .reg .u64 t; cvta.to.shared.u64 t, %1; cvt.u32.u64 %0, t; }"
        : "=r"(a) : "l"(p));
    return a;
}

__device__ __forceinline__ void cp_async16(uint32_t saddr, const void* gptr) {
    asm volatile("cp.async.cg.shared.global [%0], [%1], 16;"
                 :: "r"(saddr), "l"(gptr) : "memory");
}
__device__ __forceinline__ void cp_commit() {
    asm volatile("cp.async.commit_group;" ::: "memory");
}
template <int N>
__device__ __forceinline__ void cp_wait() {
    asm volatile("cp.async.wait_group %0;" :: "n"(N) : "memory");
}

__device__ __forceinline__ uint32_t f2tf32(float x) {
    uint32_t u;
    asm("cvt.rna.tf32.f32 %0, %1;" : "=r"(u) : "f"(x));
    return u;
}

__device__ __forceinline__ void mma_tf32(float* c, const uint32_t* a,
                                         const uint32_t* b) {
    asm volatile(
        "mma.sync.aligned.m16n8k8.row.col.f32.tf32.tf32.f32 "
        "{%0,%1,%2,%3}, {%4,%5,%6,%7}, {%8,%9}, {%0,%1,%2,%3};"
        : "+f"(c[0]), "+f"(c[1]), "+f"(c[2]), "+f"(c[3])
        : "r"(a[0]), "r"(a[1]), "r"(a[2]), "r"(a[3]), "r"(b[0]), "r"(b[1]));
}

// ---------------------------------------------------------------------------
// Kernel 1: projection GEMM via mma.sync tf32 (baseline PTX, HMMA path).
// z=0: g_ha = a @ W1[0:768];  z=1: g_hb = b @ W1[768:1536] + b1
// CTA tile 128m x 64n, K chunk 16, 2-stage cp.async pipeline.
// Grid (12, 4, 2) = 96 CTAs, 128 threads (4 warps, 2x2, warp tile 64x32).
// ---------------------------------------------------------------------------
#define ALD 20
#define BLD 72

__global__ __launch_bounds__(128) void proj_tc(
    const float* __restrict__ a, const float* __restrict__ b,
    const float* __restrict__ W1, const float* __restrict__ b1)
{
    __shared__ float As[2][128 * ALD];
    __shared__ float Bs[2][16 * BLD];

    const int tid = threadIdx.x;
    const int wid = tid >> 5;
    const int lane = tid & 31;
    const int r = lane >> 2;           // 0..7
    const int c = lane & 3;            // 0..3
    const int wm = (wid >> 1) * 64;    // warp m base
    const int wn = (wid & 1) * 32;     // warp n base

    const int n0 = blockIdx.x * 64;
    const int m0 = blockIdx.y * 128;
    const int z  = blockIdx.z;

    const float* __restrict__ X = z ? b : a;
    const float* __restrict__ W = W1 + (size_t)z * DIM * HID;

    // load assignments (cp.async, 16B each)
    const int a_r = tid >> 2;          // row within 32-row pass
    const int a_c = (tid & 3) * 4;     // k col
    const int b_r = tid >> 4;          // k row within 8-row pass
    const int b_c = (tid & 15) * 4;    // n col

    const uint32_t sA[2] = { smem_u32(As[0]), smem_u32(As[1]) };
    const uint32_t sB[2] = { smem_u32(Bs[0]), smem_u32(Bs[1]) };

    auto ldchunk = [&](int chunk, int s) {
        const int k0 = chunk * 16;
        #pragma unroll
        for (int p = 0; p < 4; p++) {
            int row = p * 32 + a_r;
            cp_async16(sA[s] + (uint32_t)(row * ALD + a_c) * 4,
                       X + (size_t)(m0 + row) * DIM + k0 + a_c);
        }
        #pragma unroll
        for (int p = 0; p < 2; p++) {
            int krow = p * 8 + b_r;
            cp_async16(sB[s] + (uint32_t)(krow * BLD + b_c) * 4,
                       W + (size_t)(k0 + krow) * HID + n0 + b_c);
        }
        cp_commit();
    };

    float acc[4][4][4] = {};

    ldchunk(0, 0);

    for (int chunk = 0; chunk < 48; chunk++) {
        const int s = chunk & 1;
        if (chunk + 1 < 48) ldchunk(chunk + 1, s ^ 1);
        if (chunk + 1 < 48) cp_wait<1>(); else cp_wait<0>();
        __syncthreads();

        const float* Ab = As[s];
        const float* Bb = Bs[s];
        #pragma unroll
        for (int ks = 0; ks < 2; ks++) {
            const int kb = ks * 8;
            uint32_t af[4][4];
            #pragma unroll
            for (int mt = 0; mt < 4; mt++) {
                const float* ap = Ab + (wm + mt * 16 + r) * ALD + kb + c;
                af[mt][0] = f2tf32(ap[0]);
                af[mt][1] = f2tf32(ap[8 * ALD]);
                af[mt][2] = f2tf32(ap[4]);
                af[mt][3] = f2tf32(ap[8 * ALD + 4]);
            }
            #pragma unroll
            for (int nt = 0; nt < 4; nt++) {
                uint32_t bf[2];
                const float* bp = Bb + (kb + c) * BLD + wn + nt * 8 + r;
                bf[0] = f2tf32(bp[0]);
                bf[1] = f2tf32(bp[4 * BLD]);
                #pragma unroll
                for (int mt = 0; mt < 4; mt++)
                    mma_tf32(acc[mt][nt], af[mt], bf);
            }
        }
        __syncthreads();
    }

    // epilogue: write C (+ b1 for z=1)
    float* __restrict__ outp = z ? g_hb : g_ha;
    #pragma unroll
    for (int mt = 0; mt < 4; mt++) {
        #pragma unroll
        for (int nt = 0; nt < 4; nt++) {
            int m = m0 + wm + mt * 16 + r;
            int n = n0 + wn + nt * 8 + c * 2;
            float2 v0 = make_float2(acc[mt][nt][0], acc[mt][nt][1]);
            float2 v1 = make_float2(acc[mt][nt][2], acc[mt][nt][3]);
            if (z) {
                float2 bb = *(const float2*)&b1[n];
                v0.x += bb.x; v0.y += bb.y;
                v1.x += bb.x; v1.y += bb.y;
            }
            *(float2*)&outp[(size_t)m * HID + n] = v0;
            *(float2*)&outp[(size_t)(m + 8) * HID + n] = v1;
        }
    }
}

// ---------------------------------------------------------------------------
// Kernel 2: pairwise relu + reduce to O=2 (split-H partials)
// ---------------------------------------------------------------------------
#define HC 64
__global__ __launch_bounds__(256) void pair_kernel(const float* __restrict__ W2)
{
    const int tt = blockIdx.x;
    const int st = blockIdx.y;
    const int zb = blockIdx.z;
    const int batch = zb >> 1;
    const int hh = zb & 1;
    const int h0base = hh * (HID / 2);

    __shared__ float sha[32][HC];
    __shared__ float shT[HC][32];
    __shared__ float sw[HC * 2];

    const int tid = threadIdx.x;
    const int tq = tid & 15;
    const int sq = tid >> 4;

    const float* __restrict__ hap = g_ha + (size_t)(batch * SEQ + st * 32) * HID;
    const float* __restrict__ hbp = g_hb + (size_t)(batch * SEQ + tt * 32) * HID;

    const int lr = tid >> 3;
    const int lc = (tid & 7) * 8;
    const int tr = tid & 31;
    const int th = (tid >> 5) * 8;

    float acc[2][2][2] = {};

    for (int hc = 0; hc < HID / 2; hc += HC) {
        const int h0 = h0base + hc;

        *(float4*)&sha[lr][lc]     = *(const float4*)&hap[(size_t)lr * HID + h0 + lc];
        *(float4*)&sha[lr][lc + 4] = *(const float4*)&hap[(size_t)lr * HID + h0 + lc + 4];

        float4 v0 = *(const float4*)&hbp[(size_t)tr * HID + h0 + th];
        float4 v1 = *(const float4*)&hbp[(size_t)tr * HID + h0 + th + 4];
        shT[th + 0][tr] = v0.x;  shT[th + 1][tr] = v0.y;
        shT[th + 2][tr] = v0.z;  shT[th + 3][tr] = v0.w;
        shT[th + 4][tr] = v1.x;  shT[th + 5][tr] = v1.y;
        shT[th + 6][tr] = v1.z;  shT[th + 7][tr] = v1.w;

        if (tid < 32)
            *(float4*)&sw[tid * 4] = *(const float4*)&W2[h0 * 2 + tid * 4];
        __syncthreads();

        #pragma unroll 16
        for (int h = 0; h < HC; h++) {
            float a0 = sha[sq * 2][h];
            float a1 = sha[sq * 2 + 1][h];
            float2 bb = *(const float2*)&shT[h][tq * 2];
            float2 wv = *(const float2*)&sw[h * 2];
            float r;
            r = fmaxf(a0 + bb.x, 0.f); acc[0][0][0] += r * wv.x; acc[0][0][1] += r * wv.y;
            r = fmaxf(a0 + bb.y, 0.f); acc[0][1][0] += r * wv.x; acc[0][1][1] += r * wv.y;
            r = fmaxf(a1 + bb.x, 0.f); acc[1][0][0] += r * wv.x; acc[1][0][1] += r * wv.y;
            r = fmaxf(a1 + bb.y, 0.f); acc[1][1][0] += r * wv.x; acc[1][1][1] += r * wv.y;
        }
        __syncthreads();
    }

    float* __restrict__ pp = g_part + (size_t)hh * PAIR_TOT;
    #pragma unroll
    for (int i = 0; i < 2; i++) {
        #pragma unroll
        for (int j = 0; j < 2; j++) {
            int s = st * 32 + sq * 2 + i;
            int t = tt * 32 + tq * 2 + j;
            size_t idx = (((size_t)batch * SEQ + s) * SEQ + t) * NOUT;
            *(float2*)&pp[idx] = make_float2(acc[i][j][0], acc[i][j][1]);
        }
    }
}

// ---------------------------------------------------------------------------
// Kernel 3: deterministic combine of the two h-halves + b2.
// ---------------------------------------------------------------------------
__global__ __launch_bounds__(256) void combine_kernel(
    float* __restrict__ out, const float* __restrict__ b2)
{
    int i = blockIdx.x * 256 + threadIdx.x;
    float4 p0 = *(const float4*)&g_part[(size_t)i * 4];
    float4 p1 = *(const float4*)&g_part[(size_t)PAIR_TOT + (size_t)i * 4];
    float c0 = b2[0], c1 = b2[1];
    float4 v = make_float4(p0.x + p1.x + c0, p0.y + p1.y + c1,
                           p0.z + p1.z + c0, p0.w + p1.w + c1);
    *(float4*)&out[(size_t)i * 4] = v;
}

// ---------------------------------------------------------------------------
extern "C" void kernel_launch(void* const* d_in, const int* in_sizes, int n_in,
                              void* d_out, int out_size)
{
    const float* a  = (const float*)d_in[0];
    const float* b  = (const float*)d_in[1];
    const float* W1 = (const float*)d_in[2];
    const float* b1 = (const float*)d_in[3];
    const float* W2 = (const float*)d_in[4];
    const float* b2 = (const float*)d_in[5];
    float* out = (float*)d_out;

    proj_tc<<<dim3(HID / 64, MROWS / 128, 2), 128>>>(a, b, W1, b1);
    pair_kernel<<<dim3(SEQ / 32, SEQ / 32, BS * 2), 256>>>(W2);
    combine_kernel<<<PAIR_TOT / 4 / 256, 256>>>(out, b2);
}